// round 2
// baseline (speedup 1.0000x reference)
#include <cuda_runtime.h>
#include <math.h>

// Problem constants
#define BB   32
#define TT   2000
#define FIN  256
#define HH   1024
#define OO   256
#define NK   1280          // HH + FIN
#define NCTA 143           // ceil(1280/9)
#define TJ   9             // output columns per CTA (143*9 = 1287 >= 1280)
#define NW   8             // warps per CTA
#define KCH  (NK / NW)     // 160 K-elements per warp
#define PACKW 12           // padded row width of packed W (48B, float4-aligned)

// -------- persistent device state (static globals: no allocation) --------
__device__ float    g_wpack[(size_t)NCTA * NK * PACKW]; // ~9.1 MB packed weights
__device__ float    g_wowf[(size_t)HH * HH];            // Wo @ Wf (4 MB)
__device__ float    g_addT[(size_t)NK * BB];            // additive term, [j][b]
__device__ float    g_xiT [(size_t)HH * BB];            // xi_hidden transposed [j][b]
__device__ float    g_u   [(size_t)HH * BB];            // state u, [j][b]
__device__ float    g_v   [2][(size_t)NK * BB];         // double-buffered input vec [k][b]
__device__ unsigned g_count;
__device__ unsigned g_gen;

// -------- precompute 1: WoWf = Wo(1024x256) @ Wf(256x1024) --------
__global__ void k_wowf(const float* __restrict__ Wo, const float* __restrict__ Wf)
{
    __shared__ float sWf[256][32];
    const int bx = blockIdx.x, by = blockIdx.y;
    const int tx = threadIdx.x & 31, ty = threadIdx.x >> 5;   // ty in 0..7

    for (int idx = threadIdx.x; idx < 256 * 32; idx += 256) {
        int o = idx >> 5, c = idx & 31;
        sWf[o][c] = Wf[(size_t)o * HH + bx * 32 + c];
    }
    __syncthreads();

    float acc0 = 0.f, acc1 = 0.f, acc2 = 0.f, acc3 = 0.f;
    const int row0 = by * 32 + ty;
    #pragma unroll 4
    for (int o = 0; o < 256; ++o) {
        float wf = sWf[o][tx];
        acc0 += Wo[(size_t)(row0      ) * OO + o] * wf;
        acc1 += Wo[(size_t)(row0 +  8 ) * OO + o] * wf;
        acc2 += Wo[(size_t)(row0 + 16 ) * OO + o] * wf;
        acc3 += Wo[(size_t)(row0 + 24 ) * OO + o] * wf;
    }
    const int col = bx * 32 + tx;
    g_wowf[(size_t)(row0      ) * HH + col] = acc0;
    g_wowf[(size_t)(row0 +  8 ) * HH + col] = acc1;
    g_wowf[(size_t)(row0 + 16 ) * HH + col] = acc2;
    g_wowf[(size_t)(row0 + 24 ) * HH + col] = acc3;
}

// -------- precompute 2: pack W_big into per-CTA 48B-aligned rows --------
// W_big[k][j]:
//   k<H,  j<H : 1.2*Wr[k][j] + WoWf[k][j]
//   k<H,  j>=H: Wo[k][j-H]
//   k>=H, j<H : Wi[k-H][j]
//   k>=H, j>=H: 0
__global__ void k_pack(const float* __restrict__ Wr, const float* __restrict__ Wi,
                       const float* __restrict__ Wo)
{
    const size_t total = (size_t)NCTA * NK * PACKW;
    size_t idx = (size_t)blockIdx.x * blockDim.x + threadIdx.x;
    if (idx >= total) return;
    int jj  = (int)(idx % PACKW);
    size_t r = idx / PACKW;
    int k   = (int)(r % NK);
    int cta = (int)(r / NK);
    int j   = cta * TJ + jj;

    float val = 0.f;
    if (jj < TJ && j < NK) {
        if (k < HH) {
            if (j < HH) val = 1.2f * Wr[(size_t)k * HH + j] + g_wowf[(size_t)k * HH + j];
            else        val = Wo[(size_t)k * OO + (j - HH)];
        } else {
            if (j < HH) val = Wi[(size_t)(k - HH) * HH + j];
        }
    }
    g_wpack[idx] = val;
}

// -------- precompute 3: addT, xiT, u=0, v0, barrier reset --------
__global__ void k_prep(const float* __restrict__ Wf, const float* __restrict__ xi_h,
                       const float* __restrict__ xi_o, const float* __restrict__ inputs)
{
    int idx = blockIdx.x * blockDim.x + threadIdx.x;      // over NK*BB
    if (idx >= NK * BB) return;
    int b = idx / NK;
    int j = idx % NK;                                     // j fast -> coalesced Wf reads

    float a;
    if (j < HH) {
        float s = 0.f;
        #pragma unroll 4
        for (int o = 0; o < OO; ++o)
            s += xi_o[(size_t)b * OO + o] * Wf[(size_t)o * HH + j];
        a = s;
        float xh = xi_h[(size_t)b * HH + j];
        g_xiT[(size_t)j * BB + b] = xh;
        g_u  [(size_t)j * BB + b] = 0.f;
        g_v[0][(size_t)j * BB + b] = xh;                  // r0 = tanh(0) + xi_h
    } else {
        a = xi_o[(size_t)b * OO + (j - HH)];
        g_v[0][(size_t)j * BB + b] = inputs[(size_t)b * TT * FIN + (j - HH)]; // x_0
    }
    g_addT[(size_t)j * BB + b] = a;
    if (idx == 0) { g_count = 0u; g_gen = 0u; }
}

// -------- grid barrier (monotonic count, acq_rel) --------
__device__ __forceinline__ void grid_barrier(unsigned target)
{
    __syncthreads();
    if (threadIdx.x == 0) {
        unsigned prev;
        asm volatile("atom.acq_rel.gpu.global.add.u32 %0, [%1], 1;"
                     : "=r"(prev) : "l"(&g_count) : "memory");
        if (prev == target * NCTA - 1u) {
            asm volatile("st.release.gpu.global.u32 [%0], %1;"
                         :: "l"(&g_gen), "r"(target) : "memory");
        } else {
            unsigned g;
            do {
                asm volatile("ld.acquire.gpu.global.u32 %0, [%1];"
                             : "=r"(g) : "l"(&g_gen) : "memory");
            } while (g < target);
        }
    }
    __syncthreads();
}

// -------- main persistent kernel: 2000 steps, one barrier each --------
__global__ void __launch_bounds__(256, 1)
k_main(const float* __restrict__ inputs, float* __restrict__ out)
{
    __shared__ float sred[NW][TJ][BB];   // 36 KB cross-warp partials

    const int cta  = blockIdx.x;
    const int w    = threadIdx.x >> 5;
    const int lane = threadIdx.x & 31;
    const int j0   = cta * TJ;

    const float* wp_base = g_wpack + ((size_t)cta * NK + (size_t)w * KCH) * PACKW;

    // static epilogue slot assignment: idx = tid + 256*s over 0..287
    int  e_j[2], e_b[2];
    bool e_valid[2];
    #pragma unroll
    for (int s = 0; s < 2; ++s) {
        int idx = threadIdx.x + 256 * s;
        int jj  = idx >> 5, b = idx & 31;
        int j   = j0 + jj;
        e_valid[s] = (idx < TJ * BB) && (j < NK);
        e_j[s] = j; e_b[s] = b;
    }

    for (int t = 0; t < TT; ++t) {
        const float* vc = g_v[t & 1] + (size_t)(w * KCH) * BB + lane;
        float*       vn = g_v[(t + 1) & 1];

        // prefetch next-step x for the z-column owners (hidden behind the GEMM)
        float xv[2] = {0.f, 0.f};
        #pragma unroll
        for (int s = 0; s < 2; ++s) {
            if (e_valid[s] && e_j[s] >= HH && (t + 1) < TT)
                xv[s] = __ldg(&inputs[(size_t)e_b[s] * TT * FIN +
                                      (size_t)(t + 1) * FIN + (e_j[s] - HH)]);
        }

        // K-chunk dot products: v-load coalesced (+streaming), W uniform from L1
        float a0=0.f,a1=0.f,a2=0.f,a3=0.f,a4=0.f,a5=0.f,a6=0.f,a7=0.f,a8=0.f;
        const float4* wp = (const float4*)wp_base;
        #pragma unroll 4
        for (int k = 0; k < KCH; ++k) {
            float  vb = __ldcs(vc + (size_t)k * BB);
            float4 w0 = __ldg(wp + 3 * k);
            float4 w1 = __ldg(wp + 3 * k + 1);
            float  w2 = __ldg((const float*)(wp + 3 * k + 2));
            a0 += vb * w0.x; a1 += vb * w0.y; a2 += vb * w0.z; a3 += vb * w0.w;
            a4 += vb * w1.x; a5 += vb * w1.y; a6 += vb * w1.z; a7 += vb * w1.w;
            a8 += vb * w2;
        }
        sred[w][0][lane] = a0; sred[w][1][lane] = a1; sred[w][2][lane] = a2;
        sred[w][3][lane] = a3; sred[w][4][lane] = a4; sred[w][5][lane] = a5;
        sred[w][6][lane] = a6; sred[w][7][lane] = a7; sred[w][8][lane] = a8;
        __syncthreads();

        // epilogue: reduce over warps, Euler update + tanh, or emit z
        #pragma unroll
        for (int s = 0; s < 2; ++s) {
            if (!e_valid[s]) continue;
            const int j = e_j[s], b = e_b[s], jj = j - j0;
            float sum = 0.f;
            #pragma unroll
            for (int ww = 0; ww < NW; ++ww) sum += sred[ww][jj][b];
            sum += g_addT[(size_t)j * BB + b];
            if (j < HH) {
                float u  = g_u[(size_t)j * BB + b];
                float un = u + 0.1f * (sum - u);           // DT/TAU = 0.1
                g_u[(size_t)j * BB + b] = un;
                vn[(size_t)j * BB + b]  = tanhf(un) + g_xiT[(size_t)j * BB + b];
            } else {
                out[(size_t)b * TT * OO + (size_t)t * OO + (j - HH)] = sum;
                if ((t + 1) < TT) vn[(size_t)j * BB + b] = xv[s];
            }
        }

        grid_barrier((unsigned)(t + 1));
    }
}

extern "C" void kernel_launch(void* const* d_in, const int* in_sizes, int n_in,
                              void* d_out, int out_size)
{
    const float* inputs = (const float*)d_in[0];   // [32,2000,256]
    const float* Wr     = (const float*)d_in[1];   // [1024,1024]
    const float* Wi     = (const float*)d_in[2];   // [256,1024]
    const float* Wf     = (const float*)d_in[3];   // [256,1024]
    const float* Wo     = (const float*)d_in[4];   // [1024,256]
    const float* xi_h   = (const float*)d_in[5];   // [32,1024]
    const float* xi_o   = (const float*)d_in[6];   // [32,256]
    float*       out    = (float*)d_out;           // [32,2000,256]

    (void)in_sizes; (void)n_in; (void)out_size;

    // precompute (runs each replay; deterministic, cheap)
    k_wowf<<<dim3(32, 32), 256>>>(Wo, Wf);
    {
        size_t total = (size_t)NCTA * NK * PACKW;
        int blocks = (int)((total + 255) / 256);
        k_pack<<<blocks, 256>>>(Wr, Wi, Wo);
    }
    k_prep<<<(NK * BB + 255) / 256, 256>>>(Wf, xi_h, xi_o, inputs);

    // persistent time loop
    k_main<<<NCTA, 256>>>(inputs, out);
}

// round 3
// speedup vs baseline: 2.1695x; 2.1695x over previous
#include <cuda_runtime.h>
#include <math.h>

// ---------------- problem constants ----------------
#define BB   32
#define TT   2000
#define FIN  256
#define HH   1024
#define OO   256
#define NJ   1280          // step-GEMM output cols (H hidden + O z-cols)
#define KK   1024          // step-GEMM K (= H)

// ---------------- main-loop tiling ----------------
#define JT   40            // j per tile  (32 tiles * 40 = 1280)
#define KG   256           // K per group (4 groups * 256 = 1024)
#define NCTA 128           // 32 j-tiles x 4 K-groups, 1 CTA/SM
#define NTHR 256
#define NW   8
#define KW   32            // K per warp (KG/NW)
#define PACK 12            // padded floats per (k, jlane) = 48B
#define SRS  36            // sred row stride (pad vs 32 to kill bank conflicts)

// ---------------- persistent device state ----------------
__device__ float    g_w[(size_t)KK * NJ];                     // [1.2Wr+WoWf | Wo]  5 MB
__device__ float    g_wpack[(size_t)NCTA * KG * 4 * PACK];    // per-CTA packed W   6.3 MB
__device__ float    g_xwi[(size_t)TT * KK * BB];              // x_t @ Wi [t][j][b] 262 MB
__device__ float    g_c[(size_t)NJ * BB];                     // const add [j][b]
__device__ float    g_xiT[(size_t)KK * BB];                   // xi_hidden [j][b]
__device__ float    g_du[3][(size_t)NJ * BB];                 // triple-buffered reduce
__device__ unsigned g_count;
__device__ unsigned g_gen;

// ============ precompute 1: g_w = [1.2*Wr + Wo@Wf | Wo] ============
__global__ void k_wcomb(const float* __restrict__ Wr, const float* __restrict__ Wo,
                        const float* __restrict__ Wf)
{
    const int bx = blockIdx.x;            // 0..39: 0..31 hidden j, 32..39 z cols
    const int by = blockIdx.y;            // 0..31 over k
    const int tx = threadIdx.x & 31, ty = threadIdx.x >> 5;

    if (bx < 32) {
        __shared__ float sWf[256][32];
        for (int idx = threadIdx.x; idx < 256 * 32; idx += 256) {
            int o = idx >> 5, c = idx & 31;
            sWf[o][c] = Wf[(size_t)o * HH + bx * 32 + c];
        }
        __syncthreads();
        float acc0 = 0.f, acc1 = 0.f, acc2 = 0.f, acc3 = 0.f;
        const int row0 = by * 32 + ty;
        #pragma unroll 4
        for (int o = 0; o < 256; ++o) {
            float wf = sWf[o][tx];
            acc0 += Wo[(size_t)(row0     ) * OO + o] * wf;
            acc1 += Wo[(size_t)(row0 +  8) * OO + o] * wf;
            acc2 += Wo[(size_t)(row0 + 16) * OO + o] * wf;
            acc3 += Wo[(size_t)(row0 + 24) * OO + o] * wf;
        }
        const int col = bx * 32 + tx;
        g_w[(size_t)(row0     ) * NJ + col] = 1.2f * Wr[(size_t)(row0     ) * HH + col] + acc0;
        g_w[(size_t)(row0 +  8) * NJ + col] = 1.2f * Wr[(size_t)(row0 +  8) * HH + col] + acc1;
        g_w[(size_t)(row0 + 16) * NJ + col] = 1.2f * Wr[(size_t)(row0 + 16) * HH + col] + acc2;
        g_w[(size_t)(row0 + 24) * NJ + col] = 1.2f * Wr[(size_t)(row0 + 24) * HH + col] + acc3;
    } else {
        const int oc = (bx - 32) * 32 + tx;
        const int row0 = by * 32 + ty;
        #pragma unroll
        for (int s = 0; s < 4; ++s) {
            int r = row0 + 8 * s;
            g_w[(size_t)r * NJ + HH + oc] = Wo[(size_t)r * OO + oc];
        }
    }
}

// ============ precompute 2: pack W into per-CTA 48B rows ============
// layout: g_wpack[cta][k(0..255)][jlane(0..3)][12]; j = jt*40 + jlane*10 + i
__global__ void k_pack()
{
    const size_t total = (size_t)NCTA * KG * 4 * PACK;
    size_t idx = (size_t)blockIdx.x * blockDim.x + threadIdx.x;
    if (idx >= total) return;
    int i     = (int)(idx % PACK);
    size_t r  = idx / PACK;
    int jlane = (int)(r % 4);
    r /= 4;
    int k     = (int)(r % KG);
    int cta   = (int)(r / KG);
    int jt = cta >> 2, kg = cta & 3;
    float v = 0.f;
    if (i < 10) {
        int j  = jt * JT + jlane * 10 + i;
        int gk = kg * KG + k;
        v = g_w[(size_t)gk * NJ + j];
    }
    g_wpack[idx] = v;
}

// ============ precompute 3: c, xiT ============
__global__ void k_prep(const float* __restrict__ Wf, const float* __restrict__ xi_h,
                       const float* __restrict__ xi_o)
{
    int idx = blockIdx.x * blockDim.x + threadIdx.x;   // over NJ*BB
    if (idx >= NJ * BB) return;
    int b = idx / NJ;
    int j = idx % NJ;
    float a;
    if (j < HH) {
        float s = 0.f;
        #pragma unroll 4
        for (int o = 0; o < OO; ++o)
            s += xi_o[(size_t)b * OO + o] * Wf[(size_t)o * HH + j];
        a = s;
        g_xiT[(size_t)j * BB + b] = xi_h[(size_t)b * HH + j];
    } else {
        a = xi_o[(size_t)b * OO + (j - HH)];
    }
    g_c[(size_t)j * BB + b] = a;
}

// ============ precompute 4: zero du + barrier counters ============
__global__ void k_zero()
{
    int idx = blockIdx.x * blockDim.x + threadIdx.x;
    if (idx < 3 * NJ * BB) ((float*)g_du)[idx] = 0.f;
    if (idx == 0) { g_count = 0u; g_gen = 0u; }
}

// ============ precompute 5: XWi[t][j][b] = (x_t @ Wi)[b][j] ============
__global__ void __launch_bounds__(256)
k_xwi(const float* __restrict__ inputs, const float* __restrict__ Wi)
{
    __shared__ float sxT[256][32];       // x_t transposed [f][b]
    const int t   = blockIdx.y;
    const int j0  = blockIdx.x * 256;
    const int tid = threadIdx.x;

    {
        int b  = tid >> 3;
        int fg = tid & 7;
        const float* row = inputs + ((size_t)b * TT + t) * FIN + fg * 32;
        #pragma unroll
        for (int i = 0; i < 8; ++i) {
            float4 v = *(const float4*)(row + 4 * i);
            int f = fg * 32 + 4 * i;
            sxT[f + 0][b] = v.x; sxT[f + 1][b] = v.y;
            sxT[f + 2][b] = v.z; sxT[f + 3][b] = v.w;
        }
    }
    __syncthreads();

    const int w     = tid >> 5;
    const int lane  = tid & 31;
    const int jlane = lane >> 3;
    const int b4    = (lane & 7) * 4;
    const int jbase = j0 + w * 32 + jlane * 8;

    float acc[8][4];
    #pragma unroll
    for (int a = 0; a < 8; ++a)
        #pragma unroll
        for (int c = 0; c < 4; ++c) acc[a][c] = 0.f;

    const float* wp = Wi + jbase;
    #pragma unroll 4
    for (int f = 0; f < 256; ++f) {
        float4 xv = *(const float4*)&sxT[f][b4];
        float4 w0 = __ldg((const float4*)(wp + (size_t)f * HH));
        float4 w1 = __ldg((const float4*)(wp + (size_t)f * HH + 4));
        acc[0][0] += w0.x * xv.x; acc[0][1] += w0.x * xv.y; acc[0][2] += w0.x * xv.z; acc[0][3] += w0.x * xv.w;
        acc[1][0] += w0.y * xv.x; acc[1][1] += w0.y * xv.y; acc[1][2] += w0.y * xv.z; acc[1][3] += w0.y * xv.w;
        acc[2][0] += w0.z * xv.x; acc[2][1] += w0.z * xv.y; acc[2][2] += w0.z * xv.z; acc[2][3] += w0.z * xv.w;
        acc[3][0] += w0.w * xv.x; acc[3][1] += w0.w * xv.y; acc[3][2] += w0.w * xv.z; acc[3][3] += w0.w * xv.w;
        acc[4][0] += w1.x * xv.x; acc[4][1] += w1.x * xv.y; acc[4][2] += w1.x * xv.z; acc[4][3] += w1.x * xv.w;
        acc[5][0] += w1.y * xv.x; acc[5][1] += w1.y * xv.y; acc[5][2] += w1.y * xv.z; acc[5][3] += w1.y * xv.w;
        acc[6][0] += w1.z * xv.x; acc[6][1] += w1.z * xv.y; acc[6][2] += w1.z * xv.z; acc[6][3] += w1.z * xv.w;
        acc[7][0] += w1.w * xv.x; acc[7][1] += w1.w * xv.y; acc[7][2] += w1.w * xv.z; acc[7][3] += w1.w * xv.w;
    }

    #pragma unroll
    for (int a = 0; a < 8; ++a) {
        float4 o; o.x = acc[a][0]; o.y = acc[a][1]; o.z = acc[a][2]; o.w = acc[a][3];
        *(float4*)&g_xwi[((size_t)t * KK + (jbase + a)) * BB + b4] = o;
    }
}

// ============ grid barrier (monotonic count, acq_rel) ============
__device__ __forceinline__ void grid_barrier(unsigned target)
{
    __syncthreads();
    if (threadIdx.x == 0) {
        unsigned prev;
        asm volatile("atom.acq_rel.gpu.global.add.u32 %0, [%1], 1;"
                     : "=r"(prev) : "l"(&g_count) : "memory");
        if (prev == target * NCTA - 1u) {
            asm volatile("st.release.gpu.global.u32 [%0], %1;"
                         :: "l"(&g_gen), "r"(target) : "memory");
        } else {
            unsigned g;
            do {
                asm volatile("ld.acquire.gpu.global.u32 %0, [%1];"
                             : "=r"(g) : "l"(&g_gen) : "memory");
            } while (g < target);
        }
    }
    __syncthreads();
}

// ============ persistent main loop ============
__global__ void __launch_bounds__(NTHR, 1)
k_main(float* __restrict__ out)
{
    extern __shared__ float smem[];
    float* sv   = smem;                   // [KG][BB]  r values (v)
    float* su   = sv  + KG * BB;          // [KG][BB]  u state
    float* sxi  = su  + KG * BB;          // [KG][BB]  xi_hidden
    float* sc   = sxi + KG * BB;          // [KG][BB]  const add (+ xwi later)
    float* sred = sc  + KG * BB;          // [NW][JT][SRS] partials

    const int cta   = blockIdx.x;
    const int tid   = threadIdx.x;
    const int jt    = cta >> 2;
    const int kg    = cta & 3;
    const int j0    = jt * JT;
    const int k0    = kg * KG;
    const int w     = tid >> 5;
    const int lane  = tid & 31;
    const int jlane = lane >> 3;
    const int blane = lane & 7;

    // ---- init smem replicas ----
    for (int idx = tid; idx < KG * BB; idx += NTHR) {
        int k = idx >> 5, b = idx & 31;
        float xi = g_xiT[(size_t)(k0 + k) * BB + b];
        sxi[idx] = xi;
        su[idx]  = 0.f;
        sv[idx]  = xi;                    // r0 = tanh(0) + xi_h
        sc[idx]  = g_c[(size_t)(k0 + k) * BB + b];
    }
    // z-handler constants (kg==0 CTAs emit 8 z-cols each)
    const int jz = HH + jt * 8 + (tid & 7);
    const int bz = tid >> 3;
    float cz = 0.f;
    if (kg == 0) cz = g_c[(size_t)jz * BB + bz];
    __syncthreads();

    const float* wp_base = g_wpack +
        (((size_t)cta * KG + (size_t)w * KW) * 4 + jlane) * PACK;

    // epilogue mapping: thread owns (kt + 32m, b4..b4+3), m=0..7
    const int kt = tid >> 3;
    const int b4 = (tid & 7) * 4;

    for (int t = 0; t < TT; ++t) {
        const int p = t % 3;

        // -------- GEMM: acc[10 j][4 b] over this warp's 32 K values --------
        float acc[10][4];
        #pragma unroll
        for (int a = 0; a < 10; ++a)
            #pragma unroll
            for (int c = 0; c < 4; ++c) acc[a][c] = 0.f;

        const float* vrow = sv + (w * KW) * BB + blane * 4;
        #pragma unroll 8
        for (int k = 0; k < KW; ++k) {
            float4 v4 = *(const float4*)(vrow + k * BB);
            const float* wr = wp_base + (size_t)k * (4 * PACK);
            float4 w0 = __ldg((const float4*)(wr));
            float4 w1 = __ldg((const float4*)(wr + 4));
            float2 w2 = __ldg((const float2*)(wr + 8));
            acc[0][0] += w0.x * v4.x; acc[0][1] += w0.x * v4.y; acc[0][2] += w0.x * v4.z; acc[0][3] += w0.x * v4.w;
            acc[1][0] += w0.y * v4.x; acc[1][1] += w0.y * v4.y; acc[1][2] += w0.y * v4.z; acc[1][3] += w0.y * v4.w;
            acc[2][0] += w0.z * v4.x; acc[2][1] += w0.z * v4.y; acc[2][2] += w0.z * v4.z; acc[2][3] += w0.z * v4.w;
            acc[3][0] += w0.w * v4.x; acc[3][1] += w0.w * v4.y; acc[3][2] += w0.w * v4.z; acc[3][3] += w0.w * v4.w;
            acc[4][0] += w1.x * v4.x; acc[4][1] += w1.x * v4.y; acc[4][2] += w1.x * v4.z; acc[4][3] += w1.x * v4.w;
            acc[5][0] += w1.y * v4.x; acc[5][1] += w1.y * v4.y; acc[5][2] += w1.y * v4.z; acc[5][3] += w1.y * v4.w;
            acc[6][0] += w1.z * v4.x; acc[6][1] += w1.z * v4.y; acc[6][2] += w1.z * v4.z; acc[6][3] += w1.z * v4.w;
            acc[7][0] += w1.w * v4.x; acc[7][1] += w1.w * v4.y; acc[7][2] += w1.w * v4.z; acc[7][3] += w1.w * v4.w;
            acc[8][0] += w2.x * v4.x; acc[8][1] += w2.x * v4.y; acc[8][2] += w2.x * v4.z; acc[8][3] += w2.x * v4.w;
            acc[9][0] += w2.y * v4.x; acc[9][1] += w2.y * v4.y; acc[9][2] += w2.y * v4.z; acc[9][3] += w2.y * v4.w;
        }
        #pragma unroll
        for (int a = 0; a < 10; ++a) {
            float4 o; o.x = acc[a][0]; o.y = acc[a][1]; o.z = acc[a][2]; o.w = acc[a][3];
            *(float4*)&sred[((size_t)w * JT + (jlane * 10 + a)) * SRS + blane * 4] = o;
        }
        __syncthreads();

        // -------- prefetch XWi for epilogue (hides DRAM behind reduce+barrier) ----
        float4 xw[8];
        #pragma unroll
        for (int m = 0; m < 8; ++m) {
            int kk = kt + 32 * m;
            xw[m] = __ldcs((const float4*)&g_xwi[((size_t)t * KK + (k0 + kk)) * BB + b4]);
        }

        // -------- cross-warp reduce + RED.f32 into g_du[p] --------
        #pragma unroll
        for (int s = 0; s < 5; ++s) {
            int o  = tid + NTHR * s;        // 0..1279 over 40j x 32b
            int jj = o >> 5, b = o & 31;
            float r = 0.f;
            #pragma unroll
            for (int ww = 0; ww < NW; ++ww)
                r += sred[((size_t)ww * JT + jj) * SRS + b];
            atomicAdd(&g_du[p][(size_t)(j0 + jj) * BB + b], r);
        }

        grid_barrier((unsigned)(t + 1));

        // -------- zero the step-(t+2) buffer slice --------
        {
            float* dz = g_du[(t + 2) % 3] + (size_t)cta * 320;
            #pragma unroll
            for (int s = 0; s < 2; ++s) { int i = tid + NTHR * s; if (i < 320) dz[i] = 0.f; }
        }
        // -------- z output (kg==0 CTAs) --------
        if (kg == 0) {
            float val = __ldcs(&g_du[p][(size_t)jz * BB + bz]) + cz;
            out[((size_t)bz * TT + t) * OO + (jz - HH)] = val;
        }
        // -------- epilogue: Euler update + tanh into own smem replica --------
        #pragma unroll
        for (int m = 0; m < 8; ++m) {
            int kk  = kt + 32 * m;
            int idx = kk * BB + b4;
            float4 d  = __ldcs((const float4*)&g_du[p][(size_t)(k0 + kk) * BB + b4]);
            float4 u  = *(float4*)&su[idx];
            float4 cc = *(float4*)&sc[idx];
            float4 xi = *(float4*)&sxi[idx];
            float4 un, vv;
            un.x = u.x + 0.1f * ((d.x + xw[m].x + cc.x) - u.x);
            un.y = u.y + 0.1f * ((d.y + xw[m].y + cc.y) - u.y);
            un.z = u.z + 0.1f * ((d.z + xw[m].z + cc.z) - u.z);
            un.w = u.w + 0.1f * ((d.w + xw[m].w + cc.w) - u.w);
            vv.x = tanhf(un.x) + xi.x;
            vv.y = tanhf(un.y) + xi.y;
            vv.z = tanhf(un.z) + xi.z;
            vv.w = tanhf(un.w) + xi.w;
            *(float4*)&su[idx] = un;
            *(float4*)&sv[idx] = vv;
        }
        __syncthreads();
    }
}

// ============ launch ============
extern "C" void kernel_launch(void* const* d_in, const int* in_sizes, int n_in,
                              void* d_out, int out_size)
{
    const float* inputs = (const float*)d_in[0];   // [32,2000,256]
    const float* Wr     = (const float*)d_in[1];   // [1024,1024]
    const float* Wi     = (const float*)d_in[2];   // [256,1024]
    const float* Wf     = (const float*)d_in[3];   // [256,1024]
    const float* Wo     = (const float*)d_in[4];   // [1024,256]
    const float* xi_h   = (const float*)d_in[5];   // [32,1024]
    const float* xi_o   = (const float*)d_in[6];   // [32,256]
    float*       out    = (float*)d_out;           // [32,2000,256]
    (void)in_sizes; (void)n_in; (void)out_size;

    const int SMEM_MAIN = (4 * KG * BB + NW * JT * SRS) * (int)sizeof(float); // 177,152 B
    cudaFuncSetAttribute(k_main, cudaFuncAttributeMaxDynamicSharedMemorySize, SMEM_MAIN);

    // precompute (each replay; deterministic)
    k_wcomb<<<dim3(40, 32), 256>>>(Wr, Wo, Wf);
    k_pack<<<(int)(((size_t)NCTA * KG * 4 * PACK + 255) / 256), 256>>>();
    k_prep<<<(NJ * BB + 255) / 256, 256>>>(Wf, xi_h, xi_o);
    k_zero<<<(3 * NJ * BB + 255) / 256, 256>>>();
    k_xwi<<<dim3(KK / 256, TT), 256>>>(inputs, Wi);

    // persistent time loop
    k_main<<<NCTA, NTHR, SMEM_MAIN>>>(out);
}